// round 17
// baseline (speedup 1.0000x reference)
#include <cuda_runtime.h>
#include <cuda_bf16.h>
#include <math.h>

// ---------------------------------------------------------------------------
// CFGGraphEncoder: 3-layer GCN-style encoder.
// R14 profile: gather was MIO/LSU-bound (issue 64%, L1 73%, L2 only 17%) --
// the fused shuffle/LDS epilogue GEMM was the cost, not the loads.
// Fix: (sum_c y[c] + 2y[n]) @ W == sum_c(y[c]@W) + 2(y[n]@W), so gather in
// y-space (pure aggregation, no GEMM) and apply W afterwards in a separate
// register-tiled GEMM kernel (no shuffles). Layer 1 stays h-space (GEMM
// before gather via dense11); its tanh fuses into gather1.
// Pipeline: scatter | dense11(h1->A) | gather1(A->B, tanh+b1, out col0) |
// gather2(B->A raw) | gemm2(A->B, tanh W2 b2, out col32) |
// gather3(B->A raw, cnt-reset) | gemm3(A->out col64).
// __device__ globals only referenced in device code (HMM lesson, R5-R7).
// ---------------------------------------------------------------------------

#define N_MAX 131072
#define SLOT  48
#define WPB   8
#define FULL  0xffffffffu

__device__ __align__(128) int   g_cnt[N_MAX];             // per-row fill count
__device__ __align__(128) int   g_csr[N_MAX * SLOT];      // fixed-stride rows
__device__ int   g_hist[64];
__device__ __align__(128) float g_ha[(N_MAX + 1) * 32];   // row N_MAX stays 0
__device__ __align__(128) float g_hb[(N_MAX + 1) * 32];   // row N_MAX stays 0

// ---------------------------------------------------------------------------
// K1: direct scatter into fixed-slot CSR + warp-aggregated bincount.
// g_cnt == 0 on entry (module-load zero; restored by gather3 each call).
// Slots >= len are never written by any call -> remain 0 -> gather must
// select away out-of-range slots (c -> N_MAX zero row).
// ---------------------------------------------------------------------------
__global__ void k_scatter_bhist(const int* __restrict__ ei,
                                const int* __restrict__ bi, int E, int N) {
    int e = blockIdx.x * blockDim.x + threadIdx.x;
    if (e < E) {
        int r = ei[e];
        int c = ei[E + e];
        int pos = atomicAdd(&g_cnt[r], 1);
        if (pos < SLOT) g_csr[r * SLOT + pos] = c;
    }
    if (e < N) {
        int b = bi[e];
        unsigned mask = __match_any_sync(__activemask(), b);
        int leader = __ffs(mask) - 1;
        if ((threadIdx.x & 31) == leader) atomicAdd(&g_hist[b], __popc(mask));
    }
}

// ---------------------------------------------------------------------------
// K2: dense h1 = x0 @ W1 -> g_ha. One warp per node, lane = out feature.
// Block 0 publishes graph_sizes (hist complete after K1).
// ---------------------------------------------------------------------------
__global__ __launch_bounds__(WPB * 32)
void k_dense11(const float* __restrict__ x0,
               const float* __restrict__ W,   // [11, 32]
               int N, float* __restrict__ out_tail) {
    __shared__ float Ws[11 * 32];
    for (int i = threadIdx.x; i < 11 * 32; i += blockDim.x) Ws[i] = W[i];
    if (blockIdx.x == 0 && threadIdx.x < 64)
        out_tail[threadIdx.x] = (float)g_hist[threadIdx.x];
    __syncthreads();

    int warp = threadIdx.x >> 5;
    int lane = threadIdx.x & 31;
    int n = blockIdx.x * WPB + warp;
    if (n >= N) return;

    float v = (lane < 11) ? __ldg(&x0[(long long)n * 11 + lane]) : 0.0f;
    float acc = 0.0f;
#pragma unroll
    for (int f = 0; f < 11; f++)
        acc = fmaf(__shfl_sync(FULL, v, f), Ws[f * 32 + lane], acc);
    g_ha[n * 32 + lane] = acc;
}

// ---------------------------------------------------------------------------
// K3/K4/K6: PURE aggregation: t[n] = sum_c in[c] + 2*in[n]  (+tanh+b if ACT)
// One warp per node. grp=lane>>3 picks one of 4 rows per warp-LDG.128,
// sub=lane&7 picks the float4 within the 128B row. Neighbor indices loaded
// directly (broadcast within group) -- no shuffles in the loop. Out-of-range
// slots select the zero row N_MAX. Reduce/transpose as verified in R14.
// SRC/DST: 1=g_ha 2=g_hb. ACT: apply tanh(+bias) and also write out96.
// ZH: zero hist (gather1). ZC: zero cnt (gather3).
// ---------------------------------------------------------------------------
template <int SRC, int DST, bool ACT, bool ZH, bool ZC>
__global__ __launch_bounds__(WPB * 32)
void k_gather(const float* __restrict__ bvec,   // [32] bias (ACT only)
              float* __restrict__ out96,        // (ACT only)
              int N, int col) {
    if (ZH && blockIdx.x == 0 && threadIdx.x < 64) g_hist[threadIdx.x] = 0;

    const float* __restrict__ h_in = (SRC == 1) ? (const float*)g_ha
                                                : (const float*)g_hb;
    int warp = threadIdx.x >> 5;
    int lane = threadIdx.x & 31;
    int n = blockIdx.x * WPB + warp;
    if (n >= N) return;            // warp-uniform exit

    int grp = lane >> 3;           // 0..3
    int sub = lane & 7;            // 0..7
    const float4* __restrict__ hb4 = (const float4*)h_in + sub;  // + c*8/row

    float self2 = 2.0f * __ldg(&h_in[n * 32 + lane]);
    int len = min(g_cnt[n], SLOT);
    if (ZC && lane == 0) g_cnt[n] = 0;      // restore invariant for next call
    const int* crow = &g_csr[n * SLOT];

    float4 acc = make_float4(0.f, 0.f, 0.f, 0.f);
    int jmax = (len + 3) >> 2;
    for (int j = 0; j < jmax; j++) {
        int slot = j * 4 + grp;
        int ci = __ldg(&crow[slot]);        // in-bounds always (slot < SLOT)
        int c = (slot < len) ? ci : N_MAX;  // zero row for padding
        float4 v = __ldg(hb4 + c * 8);
        acc.x += v.x; acc.y += v.y; acc.z += v.z; acc.w += v.w;
    }

    // reduce across the 4 row-groups (lane bits 3,4)
#pragma unroll
    for (int d = 8; d <= 16; d <<= 1) {
        acc.x += __shfl_xor_sync(FULL, acc.x, d);
        acc.y += __shfl_xor_sync(FULL, acc.y, d);
        acc.z += __shfl_xor_sync(FULL, acc.z, d);
        acc.w += __shfl_xor_sync(FULL, acc.w, d);
    }

    // transpose to lane = feature
    int src = lane >> 2;
    float tx = __shfl_sync(FULL, acc.x, src);
    float ty = __shfl_sync(FULL, acc.y, src);
    float tz = __shfl_sync(FULL, acc.z, src);
    float tw = __shfl_sync(FULL, acc.w, src);
    int k = lane & 3;
    float s = (k == 0) ? tx : (k == 1) ? ty : (k == 2) ? tz : tw;

    s += self2;
    if (ACT) {
        float y = tanhf(s + __ldg(&bvec[lane]));
        out96[(long long)n * 96 + col + lane] = y;
        if (DST == 1) g_ha[n * 32 + lane] = y;
        else          g_hb[n * 32 + lane] = y;
    } else {
        if (DST == 1) g_ha[n * 32 + lane] = s;
        else          g_hb[n * 32 + lane] = s;
    }
}

// ---------------------------------------------------------------------------
// K5/K7: y = tanh(t @ W + b) for t = g_ha (raw aggregates).
// Register-tiled, shuffle-free: TILE=32 nodes/block, 256 threads,
// thread = (n = tid>>3, fq = tid&7) computes 4 features of one node.
// Per k-step: 1 LDS.32 (t) + 1 LDS.128 (W row chunk) + 4 FMA.
// YDST: 0 = out96 only, 2 = also write y to g_hb.
// ---------------------------------------------------------------------------
#define GT 32         // nodes per block
#define TPAD 36       // smem row pitch (16B-aligned, conflict-free)

template <int YDST>
__global__ __launch_bounds__(256)
void k_gemm_act(const float* __restrict__ W,    // [32,32] row-major
                const float* __restrict__ bvec, // [32]
                float* __restrict__ out96,
                int N, int col) {
    __shared__ float Ws[32 * 32];
    __shared__ float ts[GT * TPAD];
    __shared__ float bsh[32];

    for (int i = threadIdx.x; i < 32 * 32; i += 256) Ws[i] = W[i];
    if (threadIdx.x < 32) bsh[threadIdx.x] = bvec[threadIdx.x];

    int n  = threadIdx.x >> 3;          // 0..31
    int fq = threadIdx.x & 7;           // 0..7 (features fq*4..fq*4+3)
    int gn = blockIdx.x * GT + n;

    // stage t[gn][:] -> ts[n][:] (each thread one float4)
    if (gn < N) {
        float4 v = __ldg((const float4*)(g_ha + gn * 32) + fq);
        *(float4*)&ts[n * TPAD + fq * 4] = v;
    }
    __syncthreads();

    if (gn >= N) return;

    float a0 = 0.f, a1 = 0.f, a2 = 0.f, a3 = 0.f;
#pragma unroll
    for (int k = 0; k < 32; k++) {
        float tv = ts[n * TPAD + k];
        float4 w = *(const float4*)&Ws[k * 32 + fq * 4];
        a0 = fmaf(tv, w.x, a0);
        a1 = fmaf(tv, w.y, a1);
        a2 = fmaf(tv, w.z, a2);
        a3 = fmaf(tv, w.w, a3);
    }

    float4 y;
    y.x = tanhf(a0 + bsh[fq * 4 + 0]);
    y.y = tanhf(a1 + bsh[fq * 4 + 1]);
    y.z = tanhf(a2 + bsh[fq * 4 + 2]);
    y.w = tanhf(a3 + bsh[fq * 4 + 3]);

    *(float4*)&out96[(long long)gn * 96 + col + fq * 4] = y;
    if (YDST == 2)
        *(float4*)&g_hb[gn * 32 + fq * 4] = y;
}

// ---------------------------------------------------------------------------
// Launch: 7 kernels.
// ---------------------------------------------------------------------------
extern "C" void kernel_launch(void* const* d_in, const int* in_sizes, int n_in,
                              void* d_out, int out_size) {
    const float* x0 = (const float*)d_in[0];      // [N, 11]
    const int*   ei = (const int*)d_in[1];        // [2, E] int32
    const int*   bi = (const int*)d_in[2];        // [N]    int32
    const float* W1 = (const float*)d_in[3];
    const float* b1 = (const float*)d_in[4];
    const float* W2 = (const float*)d_in[5];
    const float* b2 = (const float*)d_in[6];
    const float* W3 = (const float*)d_in[7];
    const float* b3 = (const float*)d_in[8];
    float* out = (float*)d_out;

    int N = in_sizes[0] / 11;
    int E = in_sizes[1] / 2;
    int tail = out_size - 64;

    int eb = (E + 255) / 256;
    k_scatter_bhist<<<eb, 256>>>(ei, bi, E, N);

    int db = (N + WPB - 1) / WPB;
    k_dense11<<<db, WPB * 32>>>(x0, W1, N, out + tail);          // h1 -> A

    int gb = (N + WPB - 1) / WPB;
    int mb = (N + GT - 1) / GT;
    // gather1: A -> B with tanh+b1, writes out col0 (y1 = B)
    k_gather<1, 2, true,  true,  false><<<gb, WPB * 32>>>(b1, out, N, 0);
    // gather2: B -> A raw aggregate t2
    k_gather<2, 1, false, false, false><<<gb, WPB * 32>>>(nullptr, nullptr, N, 0);
    // gemm2: y2 = tanh(t2@W2+b2) -> B + out col32
    k_gemm_act<2><<<mb, 256>>>(W2, b2, out, N, 32);
    // gather3: B -> A raw aggregate t3, reset cnt
    k_gather<2, 1, false, false, true ><<<gb, WPB * 32>>>(nullptr, nullptr, N, 0);
    // gemm3: y3 = tanh(t3@W3+b3) -> out col64 only
    k_gemm_act<0><<<mb, 256>>>(W3, b3, out, N, 64);
}